// round 12
// baseline (speedup 1.0000x reference)
#include <cuda_runtime.h>
#include <math.h>

#define NBATCH 8
#define DPIX   147456     // 384*384
#define KBINS  256
#define BINS   50

// Scratch (device globals; no dynamic allocation allowed)
__device__ __align__(16) float g_A[NBATCH * KBINS * KBINS];  // fine 2D histogram (2 MB)
__device__ __align__(16) float g_G [BINS * KBINS];           // G[b][i]
__device__ __align__(16) float g_GT[KBINS * BINS];           // GT[i][b]
__device__ __align__(16) float g_P [2 * NBATCH * BINS * KBINS];  // P halves [is][n][b][j]
__device__ __align__(16) float g_hgram[NBATCH * BINS * BINS];
__device__ float g_mx[NBATCH * BINS];            // row marginals
__device__ __align__(16) float g_myS[NBATCH * BINS + 1];  // col marginals + grand total (memset to 0)

// ---------------- Kernel 1: nearest-cell 2D histogram + G table + out zero ----
__device__ __forceinline__ void red1(float* p, float a) {
    asm volatile("red.global.add.f32 [%0], %1;" :: "l"(p), "f"(a) : "memory");
}

__global__ void k_hist(const float* __restrict__ im1, const float* __restrict__ im2,
                       float* __restrict__ out) {
    int gid = blockIdx.x * blockDim.x + threadIdx.x;   // one float4 chunk (4 pixels)

    if (gid == 0) out[0] = 0.0f;                       // harness poisons d_out

    // fold G-table computation into the first BINS*KBINS threads
    if (gid < BINS * KBINS) {
        int b = gid / KBINS, i = gid % KBINS;
        float x = (i + 0.5f) * (1.0f / KBINS);
        float c = (b + 0.5f) * 0.02f;
        float d = 10.0f * (x - c);
        float s1 = 1.0f / (1.0f + __expf(-(d + 0.1f)));
        float s2 = 1.0f / (1.0f + __expf(-(d - 0.1f)));
        float v = s1 - s2;
        g_G [b * KBINS + i] = v;
        g_GT[i * BINS  + b] = v;
    }

    const int nchunk = (NBATCH * DPIX) / 4;
    if (gid >= nchunk) return;
    int n = gid / (DPIX / 4);   // 36864 chunks per batch, no straddle
    float4 xv = ((const float4*)im1)[gid];
    float4 yv = ((const float4*)im2)[gid];
    float* base = g_A + (size_t)n * KBINS * KBINS;

    float xs[4] = {xv.x, xv.y, xv.z, xv.w};
    float ys[4] = {yv.x, yv.y, yv.z, yv.w};
#pragma unroll
    for (int q = 0; q < 4; q++) {
        int i0 = min(KBINS - 1, (int)(xs[q] * 256.0f));
        int j0 = min(KBINS - 1, (int)(ys[q] * 256.0f));
        red1(base + i0 * KBINS + j0, 1.0f);
    }
}

// ---------------- Kernel 2: P[is][n][b][j] = sum_{i in half} G[b][i]*H[n][i][j]
// grid = 160 blocks, 128 threads
__global__ void k_stageC() {
    int blk = blockIdx.x;
    int n  = blk / 20;
    int r  = blk % 20;
    int jt = r / 10;
    int r2 = r % 10;
    int bg = r2 / 2, is = r2 % 2;
    int j  = jt * 128 + threadIdx.x;
    int b0 = bg * 10;
    int i_beg = is * 128;

    __shared__ float Gs[64][12];   // 48B rows -> float4-aligned
    float acc[10];
#pragma unroll
    for (int k = 0; k < 10; k++) acc[k] = 0.0f;

    const float* A = g_A + (size_t)n * KBINS * KBINS + j;

    for (int it = i_beg; it < i_beg + 128; it += 64) {
        __syncthreads();
        for (int t = threadIdx.x; t < 640; t += 128) {
            int ii = t / 10, k = t % 10;
            Gs[ii][k] = g_GT[(it + ii) * BINS + b0 + k];
        }
        __syncthreads();
#pragma unroll 8
        for (int ii = 0; ii < 64; ii++) {
            int i = it + ii;
            float h = A[(size_t)i * KBINS];
            float4 ga = *(const float4*)&Gs[ii][0];
            float4 gb = *(const float4*)&Gs[ii][4];
            float2 gc = *(const float2*)&Gs[ii][8];
            acc[0] += h * ga.x; acc[1] += h * ga.y; acc[2] += h * ga.z; acc[3] += h * ga.w;
            acc[4] += h * gb.x; acc[5] += h * gb.y; acc[6] += h * gb.z; acc[7] += h * gb.w;
            acc[8] += h * gc.x; acc[9] += h * gc.y;
        }
    }
    size_t pb = (((size_t)is * NBATCH + n) * BINS + b0) * KBINS + j;
#pragma unroll
    for (int k = 0; k < 10; k++) g_P[pb + (size_t)k * KBINS] = acc[k];
}

// ---------------- Kernel 3: hgram rows + marginals + total ---------------------
// grid = 400 (nb = n*50+b), 256 threads: tid = g*64 + c
__global__ void __launch_bounds__(256) k_stageD() {
    int nb = blockIdx.x;
    int n  = nb / BINS;
    __shared__ float Ps[KBINS];
    __shared__ float part[4][64];
    __shared__ float rows[64];
    int tid = threadIdx.x;
    int g = tid >> 6, c = tid & 63;

    Ps[tid] = g_P[(size_t)nb * KBINS + tid]
            + g_P[(size_t)(NBATCH * BINS + nb) * KBINS + tid];
    __syncthreads();

    float s = 0.0f;
    if (c < BINS) {
        const float* GTc = g_GT + c;
        int j0 = g * 64;
        float a0 = 0.f, a1 = 0.f, a2 = 0.f, a3 = 0.f;
#pragma unroll
        for (int j = 0; j < 64; j += 4) {
            a0 += Ps[j0 + j]     * GTc[(j0 + j)     * BINS];
            a1 += Ps[j0 + j + 1] * GTc[(j0 + j + 1) * BINS];
            a2 += Ps[j0 + j + 2] * GTc[(j0 + j + 2) * BINS];
            a3 += Ps[j0 + j + 3] * GTc[(j0 + j + 3) * BINS];
        }
        s = (a0 + a1) + (a2 + a3);
    }
    part[g][c] = s;
    __syncthreads();

    if (tid < 64) {
        float t = (part[0][tid] + part[1][tid]) + (part[2][tid] + part[3][tid]);
        if (tid < BINS) {
            g_hgram[(size_t)nb * BINS + tid] = t;
            red1(&g_myS[n * BINS + tid], t);       // col marginal (spread REDs)
        }
        rows[tid] = (tid < BINS) ? t : 0.0f;
    }
    __syncthreads();
    if (tid < 32) {
        float r = rows[tid] + rows[tid + 32];
#pragma unroll
        for (int o = 16; o; o >>= 1) r += __shfl_xor_sync(0xffffffffu, r, o);
        if (tid == 0) {
            g_mx[nb] = r;
            red1(&g_myS[NBATCH * BINS], r);        // grand total
        }
    }
}

// ---------------- Kernel 4: MI terms (cheap: all stats precomputed) ------------
// grid = 400 (nb), 64 threads
__global__ void __launch_bounds__(64) k_stageE(float* __restrict__ out) {
    int nb = blockIdx.x;
    int n  = nb / BINS;
    int c  = threadIdx.x;
    float inv = 1.0f / g_myS[NBATCH * BINS];
    float mi = 0.0f;
    if (c < BINS) {
        float p = g_hgram[(size_t)nb * BINS + c] * inv;
        float q = (g_mx[nb] * inv) * (g_myS[n * BINS + c] * inv);
        mi = p * __logf(__fdividef(p + 1e-8f, q + 1e-8f));
    }
#pragma unroll
    for (int o = 16; o; o >>= 1) mi += __shfl_xor_sync(0xffffffffu, mi, o);
    __shared__ float wsum[2];
    if ((threadIdx.x & 31) == 0) wsum[threadIdx.x >> 5] = mi;
    __syncthreads();
    if (threadIdx.x == 0) atomicAdd(out, wsum[0] + wsum[1]);
}

// ---------------- Launch -------------------------------------------------------
extern "C" void kernel_launch(void* const* d_in, const int* in_sizes, int n_in,
                              void* d_out, int out_size) {
    const float* im1 = (const float*)d_in[0];
    const float* im2 = (const float*)d_in[1];

    void* aPtr = nullptr;
    cudaGetSymbolAddress(&aPtr, g_A);
    cudaMemsetAsync(aPtr, 0, sizeof(float) * NBATCH * KBINS * KBINS);
    void* mPtr = nullptr;
    cudaGetSymbolAddress(&mPtr, g_myS);
    cudaMemsetAsync(mPtr, 0, sizeof(float) * (NBATCH * BINS + 1));

    k_hist  <<<(NBATCH * DPIX / 4 + 255) / 256, 256>>>(im1, im2, (float*)d_out);
    k_stageC<<<160, 128>>>();
    k_stageD<<<400, 256>>>();
    k_stageE<<<400, 64>>>((float*)d_out);
}

// round 13
// speedup vs baseline: 1.0869x; 1.0869x over previous
#include <cuda_runtime.h>
#include <math.h>

#define NBATCH 8
#define DPIX   147456     // 384*384
#define KBINS  256
#define BINS   50

// Scratch (device globals; no dynamic allocation allowed)
__device__ __align__(16) float g_A[NBATCH * KBINS * KBINS];  // fine 2D histogram (2 MB)
__device__ __align__(16) float g_G [BINS * KBINS];           // G[b][i]
__device__ __align__(16) float g_GT[KBINS * BINS];           // GT[i][b]
__device__ __align__(16) float g_GS[KBINS];                  // GS[i] = sum_b G[b][i] (telescoped)
__device__ __align__(16) float g_P [2 * NBATCH * BINS * KBINS];  // P halves [is][n][b][j]
__device__ __align__(16) float g_Q [2 * NBATCH * KBINS];     // Q halves [is][n][j]
__device__ __align__(16) float g_myS[NBATCH * BINS];         // col marginals (written once)
__device__ __align__(16) float g_Spart[NBATCH];              // per-n totals (written once)

// ---------------- Kernel 1: nearest-cell 2D histogram + G/GS tables + out zero -
__device__ __forceinline__ void red1(float* p, float a) {
    asm volatile("red.global.add.f32 [%0], %1;" :: "l"(p), "f"(a) : "memory");
}

__global__ void k_hist(const float* __restrict__ im1, const float* __restrict__ im2,
                       float* __restrict__ out) {
    int gid = blockIdx.x * blockDim.x + threadIdx.x;   // one float4 chunk (4 pixels)

    if (gid == 0) out[0] = 0.0f;                       // harness poisons d_out

    // fold G-table computation into the first BINS*KBINS threads
    if (gid < BINS * KBINS) {
        int b = gid / KBINS, i = gid % KBINS;
        float x = (i + 0.5f) * (1.0f / KBINS);
        float c = (b + 0.5f) * 0.02f;
        float d = 10.0f * (x - c);
        float s1 = 1.0f / (1.0f + __expf(-(d + 0.1f)));
        float s2 = 1.0f / (1.0f + __expf(-(d - 0.1f)));
        float v = s1 - s2;
        g_G [b * KBINS + i] = v;
        g_GT[i * BINS  + b] = v;
        if (b == 0) {   // GS[i] = sum_b G[b][i], telescoped closed form
            float t1 = 1.0f / (1.0f + __expf(-10.0f * x));
            float t2 = 1.0f / (1.0f + __expf(-10.0f * (x - 1.0f)));
            g_GS[i] = t1 - t2;
        }
    }

    const int nchunk = (NBATCH * DPIX) / 4;
    if (gid >= nchunk) return;
    int n = gid / (DPIX / 4);   // 36864 chunks per batch, no straddle
    float4 xv = ((const float4*)im1)[gid];
    float4 yv = ((const float4*)im2)[gid];
    float* base = g_A + (size_t)n * KBINS * KBINS;

    float xs[4] = {xv.x, xv.y, xv.z, xv.w};
    float ys[4] = {yv.x, yv.y, yv.z, yv.w};
#pragma unroll
    for (int q = 0; q < 4; q++) {
        int i0 = min(KBINS - 1, (int)(xs[q] * 256.0f));
        int j0 = min(KBINS - 1, (int)(ys[q] * 256.0f));
        red1(base + i0 * KBINS + j0, 1.0f);
    }
}

// ---------------- Kernel 2: P[is][n][b][j] (+ Q row) ---------------------------
// grid = 160 blocks, 128 threads
__global__ void k_stageC() {
    int blk = blockIdx.x;
    int n  = blk / 20;
    int r  = blk % 20;
    int jt = r / 10;
    int r2 = r % 10;
    int bg = r2 / 2, is = r2 % 2;
    int j  = jt * 128 + threadIdx.x;
    int b0 = bg * 10;
    int i_beg = is * 128;

    __shared__ float Gs[64][12];   // cols 0-9: G rows; col 10: GS
    float acc[10];
#pragma unroll
    for (int k = 0; k < 10; k++) acc[k] = 0.0f;
    float accQ = 0.0f;

    const float* A = g_A + (size_t)n * KBINS * KBINS + j;

    for (int it = i_beg; it < i_beg + 128; it += 64) {
        __syncthreads();
        for (int t = threadIdx.x; t < 640; t += 128) {
            int ii = t / 10, k = t % 10;
            Gs[ii][k] = g_GT[(it + ii) * BINS + b0 + k];
        }
        if (threadIdx.x < 64) Gs[threadIdx.x][10] = g_GS[it + threadIdx.x];
        __syncthreads();
#pragma unroll 8
        for (int ii = 0; ii < 64; ii++) {
            int i = it + ii;
            float h = A[(size_t)i * KBINS];
            float4 ga = *(const float4*)&Gs[ii][0];
            float4 gb = *(const float4*)&Gs[ii][4];
            float2 gc = *(const float2*)&Gs[ii][8];
            acc[0] += h * ga.x; acc[1] += h * ga.y; acc[2] += h * ga.z; acc[3] += h * ga.w;
            acc[4] += h * gb.x; acc[5] += h * gb.y; acc[6] += h * gb.z; acc[7] += h * gb.w;
            acc[8] += h * gc.x; acc[9] += h * gc.y;
            accQ   += h * Gs[ii][10];
        }
    }
    size_t pb = (((size_t)is * NBATCH + n) * BINS + b0) * KBINS + j;
#pragma unroll
    for (int k = 0; k < 10; k++) g_P[pb + (size_t)k * KBINS] = acc[k];
    if (bg == 0) g_Q[((size_t)is * NBATCH + n) * KBINS + j] = accQ;
}

// ---------------- Kernel 3: my[n][c] = sum_j G[c][j]*Q[n][j]; Spart[n] ---------
// grid = 8 (n), 256 threads: tid = g*64 + c
__global__ void __launch_bounds__(256) k_my() {
    int n = blockIdx.x;
    __shared__ float Qs[KBINS];
    __shared__ float part[4][64];
    __shared__ float rows[64];
    int tid = threadIdx.x;
    int g = tid >> 6, c = tid & 63;

    Qs[tid] = g_Q[(size_t)n * KBINS + tid]
            + g_Q[(size_t)(NBATCH + n) * KBINS + tid];
    __syncthreads();

    float s = 0.0f;
    if (c < BINS) {
        const float* GTc = g_GT + c;
        int j0 = g * 64;
        float a0 = 0.f, a1 = 0.f, a2 = 0.f, a3 = 0.f;
#pragma unroll
        for (int j = 0; j < 64; j += 4) {
            a0 += Qs[j0 + j]     * GTc[(j0 + j)     * BINS];
            a1 += Qs[j0 + j + 1] * GTc[(j0 + j + 1) * BINS];
            a2 += Qs[j0 + j + 2] * GTc[(j0 + j + 2) * BINS];
            a3 += Qs[j0 + j + 3] * GTc[(j0 + j + 3) * BINS];
        }
        s = (a0 + a1) + (a2 + a3);
    }
    part[g][c] = s;
    __syncthreads();

    if (tid < 64) {
        float t = (part[0][tid] + part[1][tid]) + (part[2][tid] + part[3][tid]);
        if (tid < BINS) g_myS[n * BINS + tid] = t;
        rows[tid] = (tid < BINS) ? t : 0.0f;
    }
    __syncthreads();
    if (tid < 32) {
        float r = rows[tid] + rows[tid + 32];
#pragma unroll
        for (int o = 16; o; o >>= 1) r += __shfl_xor_sync(0xffffffffu, r, o);
        if (tid == 0) g_Spart[n] = r;
    }
}

// ---------------- Kernel 4: hgram rows + mx + MI terms (fused) -----------------
// grid = 400 (nb = n*50+b), 256 threads: tid = g*64 + c
__global__ void __launch_bounds__(256) k_stageD(float* __restrict__ out) {
    int nb = blockIdx.x;
    int n  = nb / BINS;
    __shared__ float Ps[KBINS];
    __shared__ float part[4][64];
    __shared__ float rows[64];
    __shared__ float mired[64];
    __shared__ float sMx;
    int tid = threadIdx.x;
    int g = tid >> 6, c = tid & 63;

    // grand total (8 broadcast loads, issued early)
    float S = 0.0f;
#pragma unroll
    for (int k = 0; k < NBATCH; k++) S += g_Spart[k];

    Ps[tid] = g_P[(size_t)nb * KBINS + tid]
            + g_P[(size_t)(NBATCH * BINS + nb) * KBINS + tid];
    __syncthreads();

    float s = 0.0f;
    if (c < BINS) {
        const float* GTc = g_GT + c;
        int j0 = g * 64;
        float a0 = 0.f, a1 = 0.f, a2 = 0.f, a3 = 0.f;
#pragma unroll
        for (int j = 0; j < 64; j += 4) {
            a0 += Ps[j0 + j]     * GTc[(j0 + j)     * BINS];
            a1 += Ps[j0 + j + 1] * GTc[(j0 + j + 1) * BINS];
            a2 += Ps[j0 + j + 2] * GTc[(j0 + j + 2) * BINS];
            a3 += Ps[j0 + j + 3] * GTc[(j0 + j + 3) * BINS];
        }
        s = (a0 + a1) + (a2 + a3);
    }
    part[g][c] = s;
    __syncthreads();

    float t = 0.0f;
    if (tid < 64) {
        t = (part[0][tid] + part[1][tid]) + (part[2][tid] + part[3][tid]);
        rows[tid] = (tid < BINS) ? t : 0.0f;
    }
    __syncthreads();
    if (tid < 32) {
        float r = rows[tid] + rows[tid + 32];
#pragma unroll
        for (int o = 16; o; o >>= 1) r += __shfl_xor_sync(0xffffffffu, r, o);
        if (tid == 0) sMx = r;
    }
    __syncthreads();

    // MI terms for this row
    float mi = 0.0f;
    if (tid < BINS) {
        float inv = 1.0f / S;
        float p = t * inv;
        float q = (sMx * inv) * (g_myS[n * BINS + tid] * inv);
        mi = p * __logf(__fdividef(p + 1e-8f, q + 1e-8f));
    }
    if (tid < 64) mired[tid] = mi;
    __syncthreads();
    if (tid < 32) {
        float m = mired[tid] + mired[tid + 32];
#pragma unroll
        for (int o = 16; o; o >>= 1) m += __shfl_xor_sync(0xffffffffu, m, o);
        if (tid == 0) atomicAdd(out, m);
    }
}

// ---------------- Launch -------------------------------------------------------
extern "C" void kernel_launch(void* const* d_in, const int* in_sizes, int n_in,
                              void* d_out, int out_size) {
    const float* im1 = (const float*)d_in[0];
    const float* im2 = (const float*)d_in[1];

    void* aPtr = nullptr;
    cudaGetSymbolAddress(&aPtr, g_A);
    cudaMemsetAsync(aPtr, 0, sizeof(float) * NBATCH * KBINS * KBINS);

    k_hist  <<<(NBATCH * DPIX / 4 + 255) / 256, 256>>>(im1, im2, (float*)d_out);
    k_stageC<<<160, 128>>>();
    k_my    <<<8, 256>>>();
    k_stageD<<<400, 256>>>((float*)d_out);
}